// round 13
// baseline (speedup 1.0000x reference)
#include <cuda_runtime.h>
#include <cstdint>

#define N_ANCH 36864
#define PRE    6000
#define POST   300
#define NMS_T  0.7f
#define NEG_INF_F (-1e9f)
#define TOPK   1024
#define CAP    4096
#define NBINS  4096
#define MAX_ROUNDS 16

typedef unsigned long long u64;

// ---------------- scratch (static device globals; no allocation) ----------------
__device__ float4 g_boxes[N_ANCH];                  // decoded+clipped boxes
__device__ __align__(16) u64 g_keys[N_ANCH];        // (desc<<16)|idx  (unique)
__device__ int    g_hist[NBINS];                    // desc>>20; cleared by select's tail

// ---------------- 1. decode + clip + valid + key + histogram ----------------
__global__ void decode_kernel(const float4* __restrict__ anchors,
                              const float* __restrict__ cls,
                              const float4* __restrict__ reg,
                              const int* __restrict__ img_w_p,
                              const int* __restrict__ img_h_p,
                              int have_wh)
{
    __shared__ int sh[NBINS];
    int tid = threadIdx.x;                      // blockDim == 256
    for (int k = tid; k < NBINS; k += 256) sh[k] = 0;
    __syncthreads();

    int i = blockIdx.x * 256 + tid;             // grid exact: 144*256 == N_ANCH

    float4 a = anchors[i];
    float4 r = reg[i];

    float w  = __fsub_rn(a.z, a.x);
    float h  = __fsub_rn(a.w, a.y);
    float cx = __fadd_rn(a.x, __fmul_rn(0.5f, w));
    float cy = __fadd_rn(a.y, __fmul_rn(0.5f, h));
    float pcx = __fadd_rn(__fmul_rn(r.x, w), cx);
    float pcy = __fadd_rn(__fmul_rn(r.y, h), cy);
    float pw  = __fmul_rn(expf(r.z), w);
    float ph  = __fmul_rn(expf(r.w), h);

    float b0 = __fsub_rn(pcx, __fmul_rn(0.5f, pw));
    float b1 = __fsub_rn(pcy, __fmul_rn(0.5f, ph));
    float b2 = __fadd_rn(pcx, __fmul_rn(0.5f, pw));
    float b3 = __fadd_rn(pcy, __fmul_rn(0.5f, ph));

    float H = have_wh ? (float)(*img_h_p) : 1024.0f;
    float W = have_wh ? (float)(*img_w_p) : 1024.0f;
    // reference: cols 0,2 clipped by img_h; cols 1,3 by img_w
    b0 = fminf(fmaxf(b0, 0.0f), H);
    b2 = fminf(fmaxf(b2, 0.0f), H);
    b1 = fminf(fmaxf(b1, 0.0f), W);
    b3 = fminf(fmaxf(b3, 0.0f), W);

    bool valid = (__fsub_rn(b2, b0) >= 16.0f) && (__fsub_rn(b3, b1) >= 16.0f);
    float s = valid ? cls[i] : NEG_INF_F;

    g_boxes[i] = make_float4(b0, b1, b2, b3);

    // stable descending key: smaller key = higher score; idx breaks ties (stable)
    unsigned int bits = __float_as_uint(s);
    unsigned int asc  = (bits & 0x80000000u) ? ~bits : (bits | 0x80000000u);
    unsigned int desc = ~asc;
    u64 key = ((u64)desc << 16) | (unsigned int)i;
    g_keys[i] = key;

    atomicAdd(&sh[(int)(key >> 36)], 1);        // bin = desc>>20
    __syncthreads();
    for (int k = tid; k < NBINS; k += 256) {
        int v = sh[k];
        if (v) atomicAdd(&g_hist[k], v);
    }
}

// ---------------- IoU predicate (exact reference op order) ----------------
__device__ __forceinline__ int iou_gt(float4 a, float aa, float4 b, float ab)
{
    float xx1 = fmaxf(a.x, b.x);
    float yy1 = fmaxf(a.y, b.y);
    float xx2 = fminf(a.z, b.z);
    float yy2 = fminf(a.w, b.w);
    float iw  = fmaxf(__fsub_rn(xx2, xx1), 0.0f);
    float ih  = fmaxf(__fsub_rn(yy2, yy1), 0.0f);
    float inter = __fmul_rn(iw, ih);
    float den = __fadd_rn(__fsub_rn(__fadd_rn(aa, ab), inter), 1e-9f);
    float iou = __fdiv_rn(inter, den);
    return iou > NMS_T;
}

// ---------------- 2. rounds of (plan -> scatter -> shared sort -> NMS) + clear ----------------
__global__ void __launch_bounds__(1024) select_nms_kernel(float* __restrict__ out)
{
    __shared__ u64    s_cand[CAP];      // 32 KB: candidate keys (sorted asc = rank order)
    __shared__ float4 s_kb[POST];       // kept boxes, score order
    __shared__ float  s_ka[POST];
    __shared__ float4 s_cb[64];
    __shared__ float  s_ca[64];
    __shared__ u64    s_intra[64];
    __shared__ u64    s_sup;
    __shared__ int    s_wsum[32];
    __shared__ int    s_thresh, s_ctr, s_kept;

    int t = threadIdx.x;
    int lane = t & 31, warp = t >> 5;
    if (t == 0) s_kept = 0;

    u64 last_key = 0;                   // exclusive lower bound of processed keys
    int processed = 0;                  // global ranks already processed
    bool done = false;

    for (int round = 0; round < MAX_ROUNDS && !done; round++) {
        // ---- plan: 4096-bin prefix scan (4 bins/thread + shfl block scan) ----
        if (t == 0) { s_thresh = 0; s_ctr = 0; }
        __syncthreads();
        int b4 = t * 4;
        int h0 = g_hist[b4+0], h1 = g_hist[b4+1], h2 = g_hist[b4+2], h3 = g_hist[b4+3];
        int sum = h0 + h1 + h2 + h3;
        int val = sum;
#pragma unroll
        for (int o = 1; o < 32; o <<= 1) {
            int n = __shfl_up_sync(0xFFFFFFFFu, val, o);
            if (lane >= o) val += n;
        }
        if (lane == 31) s_wsum[warp] = val;
        __syncthreads();
        if (warp == 0) {
            int v = s_wsum[lane];
#pragma unroll
            for (int o = 1; o < 32; o <<= 1) {
                int n = __shfl_up_sync(0xFFFFFFFFu, v, o);
                if (lane >= o) v += n;
            }
            s_wsum[lane] = v;
        }
        __syncthreads();
        int incl = val + (warp ? s_wsum[warp - 1] : 0);
        int excl = incl - sum;
        int total = s_wsum[31];
        if (processed >= PRE || processed >= total) break;
        int target = (round + 1) * TOPK;
        if (target > total) target = total;
        if (processed >= target) continue;        // empty round; target grows next
        if (excl < target && incl >= target) {
            int run = excl;
            if (run + h0 >= target && run < target) s_thresh = b4 + 0;
            run += h0;
            if (run + h1 >= target && run < target) s_thresh = b4 + 1;
            run += h1;
            if (run + h2 >= target && run < target) s_thresh = b4 + 2;
            run += h2;
            if (run + h3 >= target && run < target) s_thresh = b4 + 3;
        }
        __syncthreads();
        int thresh = s_thresh;

        // ---- scatter candidates: keys in (last_key, thresh-bin end] ----
        {
            const ulonglong2* k2 = reinterpret_cast<const ulonglong2*>(g_keys);
            for (int i = t; i < N_ANCH / 2; i += 1024) {
                ulonglong2 kk = k2[i];
                if (kk.x > last_key && (int)(kk.x >> 36) <= thresh) {
                    int p = atomicAdd(&s_ctr, 1);
                    if (p < CAP) s_cand[p] = kk.x;
                }
                if (kk.y > last_key && (int)(kk.y >> 36) <= thresh) {
                    int p = atomicAdd(&s_ctr, 1);
                    if (p < CAP) s_cand[p] = kk.y;
                }
            }
        }
        __syncthreads();
        int ctr = s_ctr;

        if (ctr > CAP) {
            // pathological mass-tie fallback (keys unique; never runs on benchmark data):
            // bisect key space for the largest cut with count <= CAP.
            u64 cur = last_key;
            for (int b = 63; b >= 0; b--) {
                u64 try_cut = cur | (1ull << b);
                if (try_cut == cur) continue;
                int local = 0;
                for (int i = t; i < N_ANCH; i += 1024) {
                    u64 k = g_keys[i];
                    if (k > last_key && k <= try_cut) local++;
                }
                if (t == 0) s_ctr = 0;
                __syncthreads();
                atomicAdd(&s_ctr, local);
                __syncthreads();
                if (s_ctr <= CAP) cur = try_cut;
                __syncthreads();
            }
            if (t == 0) s_ctr = 0;
            __syncthreads();
            for (int i = t; i < N_ANCH; i += 1024) {
                u64 k = g_keys[i];
                if (k > last_key && k <= cur) {
                    int p = atomicAdd(&s_ctr, 1);
                    s_cand[p] = k;
                }
            }
            __syncthreads();
            ctr = s_ctr;
        }
        if (ctr == 0) continue;

        // ---- pad + bitonic sort of 4096 (ascending = score-descending rank order) ----
        for (int p = ctr + t; p < CAP; p += 1024) s_cand[p] = ~0ull;
        __syncthreads();
        for (int k = 2; k <= CAP; k <<= 1) {
            for (int j = k >> 1; j > 0; j >>= 1) {
#pragma unroll
                for (int q = 0; q < CAP / 2048; q++) {
                    int p = t + q * 1024;
                    int i   = ((p & ~(j - 1)) << 1) | (p & (j - 1));
                    int ixj = i | j;
                    bool up = ((i & k) == 0);
                    u64 x = s_cand[i], y = s_cand[ixj];
                    if (up ? (x > y) : (x < y)) { s_cand[i] = y; s_cand[ixj] = x; }
                }
                __syncthreads();
            }
        }

        // ---- NMS over this round's ranks, chunked by 64 ----
        int n_this = ctr;
        if (n_this > PRE - processed) n_this = PRE - processed;   // rank cap at 6000
        int nchunks = (n_this + 63) >> 6;
        for (int c = 0; c < nchunks; c++) {
            if (t == 0) s_sup = 0ull;
            __syncthreads();
            if (t < 64) {
                int pos = c * 64 + t;
                u64 k = s_cand[pos];
                bool live = (pos < n_this) && !((k >> 47) & 1);   // rank-capped or invalid
                float4 b = live ? g_boxes[(int)(k & 0xFFFFull)]
                                : make_float4(0.f, 0.f, 0.f, 0.f);
                s_cb[t] = b;
                s_ca[t] = __fmul_rn(__fsub_rn(b.z, b.x), __fsub_rn(b.w, b.y));
                s_intra[t] = 0ull;
                if (!live) atomicOr(&s_sup, 1ull << t);
            }
            int kept0 = s_kept;
            __syncthreads();

            // A) chunk vs already-kept
            for (int p = t; p < 64 * kept0; p += 1024) {
                int b = p & 63;
                int k2 = p >> 6;
                if (iou_gt(s_kb[k2], s_ka[k2], s_cb[b], s_ca[b]))
                    atomicOr(&s_sup, 1ull << b);
            }
            // B) intra-chunk upper triangle
            for (int p = t; p < 4096; p += 1024) {
                int i2 = p >> 6;
                int j2 = p & 63;
                if (j2 > i2 && iou_gt(s_cb[i2], s_ca[i2], s_cb[j2], s_ca[j2]))
                    atomicOr(&s_intra[i2], 1ull << j2);
            }
            __syncthreads();

            // C) serial greedy walk
            if (t == 0) {
                u64 rem = s_sup;
                int kept = kept0;
                u64 m = ~rem;
                while (m) {
                    int b = __ffsll((long long)m) - 1;
                    s_kb[kept] = s_cb[b];
                    s_ka[kept] = s_ca[b];
                    kept++;
                    if (kept >= POST) break;
                    rem |= s_intra[b];
                    m = ~rem & (~0ull << (b + 1));
                }
                s_kept = kept;
            }
            __syncthreads();
            if (s_kept >= POST) { done = true; break; }
        }
        if (done) break;
        processed += ctr;
        if (n_this < ctr) break;                 // hit rank-6000 cap
        last_key = s_cand[ctr - 1];              // largest processed key (uniform read)
        __syncthreads();
    }
    __syncthreads();

    // ---- clear histogram for next graph replay (after all plan reads) ----
    for (int k = t; k < NBINS; k += 1024) g_hist[k] = 0;

    // ---- output: kept boxes in order, zero-pad tail ----
    int kept = s_kept;
    if (t < POST) {
        float4 v = make_float4(0.f, 0.f, 0.f, 0.f);
        if (t < kept) v = s_kb[t];
        reinterpret_cast<float4*>(out)[t] = v;
    }
}

// ---------------- launch ----------------
extern "C" void kernel_launch(void* const* d_in, const int* in_sizes, int n_in,
                              void* d_out, int out_size)
{
    const float4* anchors = (const float4*)d_in[0];
    const float*  cls     = (const float*)d_in[1];
    const float4* reg     = (const float4*)d_in[2];
    const int*    img_w   = (n_in > 3) ? (const int*)d_in[3] : nullptr;
    const int*    img_h   = (n_in > 4) ? (const int*)d_in[4] : nullptr;
    int have_wh = (n_in > 4) ? 1 : 0;

    decode_kernel<<<N_ANCH / 256, 256>>>(anchors, cls, reg, img_w, img_h, have_wh);
    select_nms_kernel<<<1, 1024>>>((float*)d_out);
}

// round 14
// speedup vs baseline: 1.1597x; 1.1597x over previous
#include <cuda_runtime.h>
#include <cstdint>

#define N_ANCH 36864
#define PRE    6000
#define POST   300
#define NMS_T  0.7f
#define NEG_INF_F (-1e9f)
#define TOPK   1024
#define CAP    2048
#define MAX_ROUNDS 16

typedef unsigned long long u64;

// ---------------- scratch (static device globals; no allocation) ----------------
__device__ float4 g_boxes[N_ANCH];                  // decoded+clipped boxes
__device__ __align__(16) u64 g_keys[N_ANCH];        // (desc<<16)|idx  (unique)
__device__ int    g_hist_lo[65536];                 // fine hist (desc>>16); cleared by select tail
__device__ int    g_hist_hi[256];                   // coarse hist (desc>>24)

// ---------------- 1. decode + clip + valid + key + 2-level histogram ----------------
__global__ void decode_kernel(const float4* __restrict__ anchors,
                              const float* __restrict__ cls,
                              const float4* __restrict__ reg,
                              const int* __restrict__ img_w_p,
                              const int* __restrict__ img_h_p,
                              int have_wh)
{
    __shared__ int sh_hi[256];
    int tid = threadIdx.x;                      // blockDim == 256
    sh_hi[tid] = 0;
    __syncthreads();

    int i = blockIdx.x * 256 + tid;             // grid exact: 144*256 == N_ANCH

    float4 a = anchors[i];
    float4 r = reg[i];

    float w  = __fsub_rn(a.z, a.x);
    float h  = __fsub_rn(a.w, a.y);
    float cx = __fadd_rn(a.x, __fmul_rn(0.5f, w));
    float cy = __fadd_rn(a.y, __fmul_rn(0.5f, h));
    float pcx = __fadd_rn(__fmul_rn(r.x, w), cx);
    float pcy = __fadd_rn(__fmul_rn(r.y, h), cy);
    float pw  = __fmul_rn(expf(r.z), w);
    float ph  = __fmul_rn(expf(r.w), h);

    float b0 = __fsub_rn(pcx, __fmul_rn(0.5f, pw));
    float b1 = __fsub_rn(pcy, __fmul_rn(0.5f, ph));
    float b2 = __fadd_rn(pcx, __fmul_rn(0.5f, pw));
    float b3 = __fadd_rn(pcy, __fmul_rn(0.5f, ph));

    float H = have_wh ? (float)(*img_h_p) : 1024.0f;
    float W = have_wh ? (float)(*img_w_p) : 1024.0f;
    // reference: cols 0,2 clipped by img_h; cols 1,3 by img_w
    b0 = fminf(fmaxf(b0, 0.0f), H);
    b2 = fminf(fmaxf(b2, 0.0f), H);
    b1 = fminf(fmaxf(b1, 0.0f), W);
    b3 = fminf(fmaxf(b3, 0.0f), W);

    bool valid = (__fsub_rn(b2, b0) >= 16.0f) && (__fsub_rn(b3, b1) >= 16.0f);
    float s = valid ? cls[i] : NEG_INF_F;

    g_boxes[i] = make_float4(b0, b1, b2, b3);

    // stable descending key: smaller key = higher score; idx breaks ties (stable)
    unsigned int bits = __float_as_uint(s);
    unsigned int asc  = (bits & 0x80000000u) ? ~bits : (bits | 0x80000000u);
    unsigned int desc = ~asc;
    u64 key = ((u64)desc << 16) | (unsigned int)i;
    g_keys[i] = key;

    atomicAdd(&g_hist_lo[(int)(key >> 32)], 1);           // fine bin = desc>>16
    atomicAdd(&sh_hi[(int)((key >> 40) & 255)], 1);       // coarse bin = desc>>24
    __syncthreads();
    if (sh_hi[tid]) atomicAdd(&g_hist_hi[tid], sh_hi[tid]);
}

// ---------------- IoU predicate (exact reference op order) ----------------
__device__ __forceinline__ int iou_gt(float4 a, float aa, float4 b, float ab)
{
    float xx1 = fmaxf(a.x, b.x);
    float yy1 = fmaxf(a.y, b.y);
    float xx2 = fminf(a.z, b.z);
    float yy2 = fminf(a.w, b.w);
    float iw  = fmaxf(__fsub_rn(xx2, xx1), 0.0f);
    float ih  = fmaxf(__fsub_rn(yy2, yy1), 0.0f);
    float inter = __fmul_rn(iw, ih);
    float den = __fadd_rn(__fsub_rn(__fadd_rn(aa, ab), inter), 1e-9f);
    float iou = __fdiv_rn(inter, den);
    return iou > NMS_T;
}

// inclusive scan of 256 ints held by threads 0..255; result in s_incl[0..255].
__device__ __forceinline__ void scan256(int t, int val, int* s_incl, int* s_wsum)
{
    if (t < 256) {
#pragma unroll
        for (int o = 1; o < 32; o <<= 1) {
            int n = __shfl_up_sync(0xFFFFFFFFu, val, o);
            if ((t & 31) >= o) val += n;
        }
        if ((t & 31) == 31) s_wsum[t >> 5] = val;
    }
    __syncthreads();
    if (t < 8) {
        int v = s_wsum[t];
#pragma unroll
        for (int o = 1; o < 8; o <<= 1) {
            int n = __shfl_up_sync(0xFFu, v, o);
            if (t >= o) v += n;
        }
        s_wsum[t] = v;
    }
    __syncthreads();
    if (t < 256) s_incl[t] = val + ((t >= 32) ? s_wsum[(t >> 5) - 1] : 0);
    __syncthreads();
}

// ---------------- 2. rounds of (plan -> scatter -> shared sort -> NMS) + clear ----------------
__global__ void __launch_bounds__(1024) select_nms_kernel(float* __restrict__ out)
{
    __shared__ u64    s_cand[CAP];      // candidate keys (sorted ascending = rank order)
    __shared__ float4 s_kb[POST];       // kept boxes, score order
    __shared__ float  s_ka[POST];
    __shared__ float4 s_cb[64];
    __shared__ float  s_ca[64];
    __shared__ u64    s_intra[64];
    __shared__ u64    s_sup;
    __shared__ int    s_scan[256];
    __shared__ int    s_wsum[8];
    __shared__ int    s_H, s_baseH, s_thresh, s_ctr, s_kept;

    int t = threadIdx.x;
    if (t == 0) s_kept = 0;

    u64 last_key = 0;                   // exclusive lower bound of processed keys
    int processed = 0;                  // global ranks already processed
    bool done = false;

    for (int round = 0; round < MAX_ROUNDS && !done; round++) {
        // ---- plan: coarse scan ----
        if (t == 0) { s_H = 0; s_baseH = 0; s_thresh = 0; s_ctr = 0; }
        __syncthreads();
        scan256(t, (t < 256) ? g_hist_hi[t] : 0, s_scan, s_wsum);
        int total = s_scan[255];
        if (processed >= PRE || processed >= total) break;
        int target = (round + 1) * TOPK;
        if (target > total) target = total;
        if (processed >= target) continue;        // empty round; target grows next
        if (t < 256) {
            int incl = s_scan[t];
            int excl = t ? s_scan[t - 1] : 0;
            if (excl < target && incl >= target) { s_H = t; s_baseH = excl; }
        }
        __syncthreads();
        int Hb = s_H, baseH = s_baseH;

        // ---- plan: fine scan within coarse bin Hb ----
        scan256(t, (t < 256) ? g_hist_lo[Hb * 256 + t] : 0, s_scan, s_wsum);
        if (t < 256) {
            int incl = baseH + s_scan[t];
            int excl = baseH + (t ? s_scan[t - 1] : 0);
            if (excl < target && incl >= target) s_thresh = Hb * 256 + t;
        }
        __syncthreads();
        int thresh = s_thresh;

        // ---- scatter candidates: keys in (last_key, thresh-bin end] ----
        {
            const ulonglong2* k2 = reinterpret_cast<const ulonglong2*>(g_keys);
            for (int i = t; i < N_ANCH / 2; i += 1024) {
                ulonglong2 kk = k2[i];
                if (kk.x > last_key && (int)(kk.x >> 32) <= thresh) {
                    int p = atomicAdd(&s_ctr, 1);
                    if (p < CAP) s_cand[p] = kk.x;
                }
                if (kk.y > last_key && (int)(kk.y >> 32) <= thresh) {
                    int p = atomicAdd(&s_ctr, 1);
                    if (p < CAP) s_cand[p] = kk.y;
                }
            }
        }
        __syncthreads();
        int ctr = s_ctr;

        if (ctr > CAP) {
            // pathological mass-tie fallback (keys unique; never runs on benchmark data):
            // bisect key space for the largest cut with count <= CAP.
            u64 cur = last_key;
            for (int b = 63; b >= 0; b--) {
                u64 try_cut = cur | (1ull << b);
                if (try_cut == cur) continue;
                int local = 0;
                for (int i = t; i < N_ANCH; i += 1024) {
                    u64 k = g_keys[i];
                    if (k > last_key && k <= try_cut) local++;
                }
                if (t == 0) s_ctr = 0;
                __syncthreads();
                atomicAdd(&s_ctr, local);
                __syncthreads();
                if (s_ctr <= CAP) cur = try_cut;
                __syncthreads();
            }
            if (t == 0) s_ctr = 0;
            __syncthreads();
            for (int i = t; i < N_ANCH; i += 1024) {
                u64 k = g_keys[i];
                if (k > last_key && k <= cur) {
                    int p = atomicAdd(&s_ctr, 1);
                    s_cand[p] = k;
                }
            }
            __syncthreads();
            ctr = s_ctr;
        }
        if (ctr == 0) continue;

        // ---- pad + bitonic sort of 2048 (ascending = score-descending rank order) ----
        for (int p = ctr + t; p < CAP; p += 1024) s_cand[p] = ~0ull;
        __syncthreads();
        for (int k = 2; k <= CAP; k <<= 1) {
            for (int j = k >> 1; j > 0; j >>= 1) {
                int i   = ((t & ~(j - 1)) << 1) | (t & (j - 1));
                int ixj = i | j;
                bool up = ((i & k) == 0);
                u64 x = s_cand[i], y = s_cand[ixj];
                if (up ? (x > y) : (x < y)) { s_cand[i] = y; s_cand[ixj] = x; }
                __syncthreads();
            }
        }

        // ---- NMS over this round's ranks, chunked by 64 ----
        int n_this = ctr;
        if (n_this > PRE - processed) n_this = PRE - processed;   // rank cap at 6000
        int nchunks = (n_this + 63) >> 6;
        for (int c = 0; c < nchunks; c++) {
            if (t == 0) s_sup = 0ull;
            __syncthreads();
            if (t < 64) {
                int pos = c * 64 + t;
                u64 k = s_cand[pos];
                bool live = (pos < n_this) && !((k >> 47) & 1);   // rank-capped or invalid
                float4 b = live ? g_boxes[(int)(k & 0xFFFFull)]
                                : make_float4(0.f, 0.f, 0.f, 0.f);
                s_cb[t] = b;
                s_ca[t] = __fmul_rn(__fsub_rn(b.z, b.x), __fsub_rn(b.w, b.y));
                s_intra[t] = 0ull;
                if (!live) atomicOr(&s_sup, 1ull << t);
            }
            int kept0 = s_kept;
            __syncthreads();

            // A) chunk vs already-kept
            for (int p = t; p < 64 * kept0; p += 1024) {
                int b = p & 63;
                int k2 = p >> 6;
                if (iou_gt(s_kb[k2], s_ka[k2], s_cb[b], s_ca[b]))
                    atomicOr(&s_sup, 1ull << b);
            }
            // B) intra-chunk upper triangle
            for (int p = t; p < 4096; p += 1024) {
                int i2 = p >> 6;
                int j2 = p & 63;
                if (j2 > i2 && iou_gt(s_cb[i2], s_ca[i2], s_cb[j2], s_ca[j2]))
                    atomicOr(&s_intra[i2], 1ull << j2);
            }
            __syncthreads();

            // C) serial greedy walk
            if (t == 0) {
                u64 rem = s_sup;
                int kept = kept0;
                u64 m = ~rem;
                while (m) {
                    int b = __ffsll((long long)m) - 1;
                    s_kb[kept] = s_cb[b];
                    s_ka[kept] = s_ca[b];
                    kept++;
                    if (kept >= POST) break;
                    rem |= s_intra[b];
                    m = ~rem & (~0ull << (b + 1));
                }
                s_kept = kept;
            }
            __syncthreads();
            if (s_kept >= POST) { done = true; break; }
        }
        if (done) break;
        processed += ctr;
        if (n_this < ctr) break;                 // hit rank-6000 cap
        last_key = s_cand[ctr - 1];              // largest processed key (uniform read)
        __syncthreads();
    }
    __syncthreads();

    // ---- clear histograms for next graph replay (after all plan reads) ----
    for (int k = t; k < 65536; k += 1024) g_hist_lo[k] = 0;
    if (t < 256) g_hist_hi[t] = 0;

    // ---- output: kept boxes in order, zero-pad tail ----
    int kept = s_kept;
    if (t < POST) {
        float4 v = make_float4(0.f, 0.f, 0.f, 0.f);
        if (t < kept) v = s_kb[t];
        reinterpret_cast<float4*>(out)[t] = v;
    }
}

// ---------------- launch ----------------
extern "C" void kernel_launch(void* const* d_in, const int* in_sizes, int n_in,
                              void* d_out, int out_size)
{
    const float4* anchors = (const float4*)d_in[0];
    const float*  cls     = (const float*)d_in[1];
    const float4* reg     = (const float4*)d_in[2];
    const int*    img_w   = (n_in > 3) ? (const int*)d_in[3] : nullptr;
    const int*    img_h   = (n_in > 4) ? (const int*)d_in[4] : nullptr;
    int have_wh = (n_in > 4) ? 1 : 0;

    decode_kernel<<<N_ANCH / 256, 256>>>(anchors, cls, reg, img_w, img_h, have_wh);
    select_nms_kernel<<<1, 1024>>>((float*)d_out);
}

// round 15
// speedup vs baseline: 1.5389x; 1.3269x over previous
#include <cuda_runtime.h>
#include <cstdint>

#define N_ANCH 36864
#define PRE    6000
#define POST   300
#define NMS_T  0.7f
#define NEG_INF_F (-1e9f)
#define NTOP   512
#define NCHW   8            /* NTOP/64 */
#define TOPK_FB 1024
#define CAP    2048
#define MAX_ROUNDS 16
#define NBLK   36
#define NWORK  (NBLK - 1)
#define NTILE  36           /* 8*9/2 upper-tri 64x64 tiles */

typedef unsigned long long u64;

// ---------------- scratch (static device globals; no allocation) ----------------
__device__ float4 g_boxes[N_ANCH];
__device__ __align__(16) u64 g_keys[N_ANCH];
__device__ __align__(16) int g_hist_lo[65536];   // fine hist (desc>>16)
__device__ int    g_hist_hi[256];                // coarse hist (desc>>24)
__device__ float4 g_topbox[NTOP];
__device__ float  g_toparea[NTOP];
__device__ int    g_ntop;
__device__ u64    g_mask512[NTOP * NCHW];
__device__ int    g_sync1, g_flag2, g_sync3;     // static zero-init; reset each run

// ---------------- IoU predicate (exact reference op order) ----------------
__device__ __forceinline__ int iou_gt(float4 a, float aa, float4 b, float ab)
{
    float xx1 = fmaxf(a.x, b.x);
    float yy1 = fmaxf(a.y, b.y);
    float xx2 = fminf(a.z, b.z);
    float yy2 = fminf(a.w, b.w);
    float iw  = fmaxf(__fsub_rn(xx2, xx1), 0.0f);
    float ih  = fmaxf(__fsub_rn(yy2, yy1), 0.0f);
    float inter = __fmul_rn(iw, ih);
    float den = __fadd_rn(__fsub_rn(__fadd_rn(aa, ab), inter), 1e-9f);
    float iou = __fdiv_rn(inter, den);
    return iou > NMS_T;
}

// inclusive scan of 256 ints held by threads 0..255; result in s_incl[0..255].
__device__ __forceinline__ void scan256(int t, int val, int* s_incl, int* s_wsum)
{
    if (t < 256) {
#pragma unroll
        for (int o = 1; o < 32; o <<= 1) {
            int n = __shfl_up_sync(0xFFFFFFFFu, val, o);
            if ((t & 31) >= o) val += n;
        }
        if ((t & 31) == 31) s_wsum[t >> 5] = val;
    }
    __syncthreads();
    if (t < 8) {
        int v = s_wsum[t];
#pragma unroll
        for (int o = 1; o < 8; o <<= 1) {
            int n = __shfl_up_sync(0xFFu, v, o);
            if (t >= o) v += n;
        }
        s_wsum[t] = v;
    }
    __syncthreads();
    if (t < 256) s_incl[t] = val + ((t >= 32) ? s_wsum[(t >> 5) - 1] : 0);
    __syncthreads();
}

// ---------------- single fused kernel ----------------
__global__ void __launch_bounds__(1024) fused_kernel(
    const float4* __restrict__ anchors,
    const float*  __restrict__ cls,
    const float4* __restrict__ reg,
    const int*    __restrict__ img_w_p,
    const int*    __restrict__ img_h_p,
    int have_wh, float* __restrict__ out)
{
    __shared__ u64    s_cand[CAP];
    __shared__ float4 s_kb[POST];
    __shared__ float  s_ka[POST];
    __shared__ float4 s_cb[64];
    __shared__ float  s_ca[64];
    __shared__ u64    s_intra[64];
    __shared__ u64    s_sup;
    __shared__ u64    s_rem[NCHW];
    __shared__ unsigned short s_keep[POST];
    __shared__ unsigned char  s_wb[64];
    __shared__ int    s_scan[256];
    __shared__ int    s_wsum[8];
    __shared__ int    s_H, s_baseH, s_thresh, s_ctr, s_kept, s_m;
    __shared__ int    sh_hi[256];
    // worker tile buffers
    __shared__ float4 s_rbx[64]; __shared__ float s_rba[64];
    __shared__ float4 s_cbx[64]; __shared__ float s_cba[64];
    __shared__ u64    s_bits[64];

    int bid = blockIdx.x;
    int t   = threadIdx.x;

    // ================= phase 0: decode (all 36 blocks, 1024 anchors each) ==========
    if (t < 256) sh_hi[t] = 0;
    __syncthreads();
    {
        int i = bid * 1024 + t;               // 36*1024 == N_ANCH exactly
        float4 a = anchors[i];
        float4 r = reg[i];

        float w  = __fsub_rn(a.z, a.x);
        float h  = __fsub_rn(a.w, a.y);
        float cx = __fadd_rn(a.x, __fmul_rn(0.5f, w));
        float cy = __fadd_rn(a.y, __fmul_rn(0.5f, h));
        float pcx = __fadd_rn(__fmul_rn(r.x, w), cx);
        float pcy = __fadd_rn(__fmul_rn(r.y, h), cy);
        float pw  = __fmul_rn(expf(r.z), w);
        float ph  = __fmul_rn(expf(r.w), h);

        float b0 = __fsub_rn(pcx, __fmul_rn(0.5f, pw));
        float b1 = __fsub_rn(pcy, __fmul_rn(0.5f, ph));
        float b2 = __fadd_rn(pcx, __fmul_rn(0.5f, pw));
        float b3 = __fadd_rn(pcy, __fmul_rn(0.5f, ph));

        float H = have_wh ? (float)(*img_h_p) : 1024.0f;
        float W = have_wh ? (float)(*img_w_p) : 1024.0f;
        // reference: cols 0,2 clipped by img_h; cols 1,3 by img_w
        b0 = fminf(fmaxf(b0, 0.0f), H);
        b2 = fminf(fmaxf(b2, 0.0f), H);
        b1 = fminf(fmaxf(b1, 0.0f), W);
        b3 = fminf(fmaxf(b3, 0.0f), W);

        bool valid = (__fsub_rn(b2, b0) >= 16.0f) && (__fsub_rn(b3, b1) >= 16.0f);
        float s = valid ? cls[i] : NEG_INF_F;

        g_boxes[i] = make_float4(b0, b1, b2, b3);

        unsigned int bits = __float_as_uint(s);
        unsigned int asc  = (bits & 0x80000000u) ? ~bits : (bits | 0x80000000u);
        unsigned int desc = ~asc;
        u64 key = ((u64)desc << 16) | (unsigned int)i;
        g_keys[i] = key;

        atomicAdd(&g_hist_lo[(int)(key >> 32)], 1);
        atomicAdd(&sh_hi[(int)((key >> 40) & 255)], 1);
    }
    __syncthreads();
    if (t < 256 && sh_hi[t]) atomicAdd(&g_hist_hi[t], sh_hi[t]);
    __threadfence();
    __syncthreads();
    if (t == 0) atomicAdd(&g_sync1, 1);

    // ================= worker blocks: compute 512x512 IoU bitmask tiles ============
    if (bid != 0) {
        if (t == 0) { while (atomicAdd(&g_flag2, 0) == 0) __nanosleep(64); }
        __syncthreads();
        __threadfence();
        int ntop = g_ntop;
        for (int job = bid - 1; job < NTILE; job += NWORK) {
            int ci = 0, wj = 0;
            { int jj = job;
              for (int r2 = 0; r2 < 8; r2++) { int cnt = 8 - r2;
                  if (jj < cnt) { ci = r2; wj = r2 + jj; break; } jj -= cnt; } }
            if (t < 64) {
                int gr = ci * 64 + t, gc = wj * 64 + t;
                float4 rb = (gr < ntop) ? g_topbox[gr] : make_float4(0.f, 0.f, 0.f, 0.f);
                s_rbx[t] = rb; s_rba[t] = (gr < ntop) ? g_toparea[gr] : 0.f;
                float4 cb = (gc < ntop) ? g_topbox[gc] : make_float4(0.f, 0.f, 0.f, 0.f);
                s_cbx[t] = cb; s_cba[t] = (gc < ntop) ? g_toparea[gc] : 0.f;
                s_bits[t] = 0ull;
            }
            __syncthreads();
            {
                int p0 = t * 4;
                int row = p0 >> 6, c0 = p0 & 63;
                float4 bi = s_rbx[row]; float ai = s_rba[row];
                int gi = ci * 64 + row;
                unsigned nib = 0;
#pragma unroll
                for (int q = 0; q < 4; q++) {
                    int col = c0 + q;
                    int gj  = wj * 64 + col;
                    if (gj > gi && gi < ntop && gj < ntop &&
                        iou_gt(bi, ai, s_cbx[col], s_cba[col]))
                        nib |= 1u << q;
                }
                if (nib) atomicOr(&s_bits[row], (u64)nib << c0);
            }
            __syncthreads();
            if (t < 64) g_mask512[(ci * 64 + t) * NCHW + wj] = s_bits[t];
            __syncthreads();
        }
        __threadfence();
        __syncthreads();
        if (t == 0) atomicAdd(&g_sync3, 1);
        return;
    }

    // ================= block 0: wait decode, then topk =============================
    if (t == 0) { while (atomicAdd(&g_sync1, 0) < NBLK) __nanosleep(64); }
    __syncthreads();
    __threadfence();
    if (t == 0) { s_H = 0; s_baseH = 0; s_thresh = 0; s_ctr = 0; s_kept = 0; }
    __syncthreads();

    // plan: coarse + fine scans, target = 512
    scan256(t, (t < 256) ? g_hist_hi[t] : 0, s_scan, s_wsum);
    int total = s_scan[255];
    int target = NTOP;
    if (target > total) target = total;
    if (target > PRE)   target = PRE;
    if (t < 256) {
        int incl = s_scan[t], excl = t ? s_scan[t - 1] : 0;
        if (excl < target && incl >= target) { s_H = t; s_baseH = excl; }
    }
    __syncthreads();
    int Hb = s_H, baseH = s_baseH;
    scan256(t, (t < 256) ? g_hist_lo[Hb * 256 + t] : 0, s_scan, s_wsum);
    if (t < 256) {
        int incl = baseH + s_scan[t], excl = baseH + (t ? s_scan[t - 1] : 0);
        if (excl < target && incl >= target) s_thresh = Hb * 256 + t;
    }
    __syncthreads();
    int thresh = s_thresh;

    u64 last_key = 0;
    // scatter
    {
        const ulonglong2* k2 = reinterpret_cast<const ulonglong2*>(g_keys);
        for (int i = t; i < N_ANCH / 2; i += 1024) {
            ulonglong2 kk = k2[i];
            if ((int)(kk.x >> 32) <= thresh) {
                int p = atomicAdd(&s_ctr, 1);
                if (p < CAP) s_cand[p] = kk.x;
            }
            if ((int)(kk.y >> 32) <= thresh) {
                int p = atomicAdd(&s_ctr, 1);
                if (p < CAP) s_cand[p] = kk.y;
            }
        }
    }
    __syncthreads();
    int ctr = s_ctr;
    if (ctr > CAP) {
        // pathological mass-tie fallback (keys unique; never runs on bench data)
        u64 cur = last_key;
        for (int b = 63; b >= 0; b--) {
            u64 try_cut = cur | (1ull << b);
            if (try_cut == cur) continue;
            int local = 0;
            for (int i = t; i < N_ANCH; i += 1024) {
                u64 k = g_keys[i];
                if (k > last_key && k <= try_cut) local++;
            }
            if (t == 0) s_ctr = 0;
            __syncthreads();
            atomicAdd(&s_ctr, local);
            __syncthreads();
            if (s_ctr <= CAP) cur = try_cut;
            __syncthreads();
        }
        if (t == 0) s_ctr = 0;
        __syncthreads();
        for (int i = t; i < N_ANCH; i += 1024) {
            u64 k = g_keys[i];
            if (k > last_key && k <= cur) {
                int p = atomicAdd(&s_ctr, 1);
                s_cand[p] = k;
            }
        }
        __syncthreads();
        ctr = s_ctr;
    }

    // sort (1024 if possible, else 2048)
    int n_sort = (ctr <= 1024) ? 1024 : 2048;
    for (int p = ctr + t; p < n_sort; p += 1024) s_cand[p] = ~0ull;
    __syncthreads();
    for (int k = 2; k <= n_sort; k <<= 1) {
        for (int j = k >> 1; j > 0; j >>= 1) {
            if (t < (n_sort >> 1)) {
                int i   = ((t & ~(j - 1)) << 1) | (t & (j - 1));
                int ixj = i | j;
                bool up = ((i & k) == 0);
                u64 x = s_cand[i], y = s_cand[ixj];
                if (up ? (x > y) : (x < y)) { s_cand[i] = y; s_cand[ixj] = x; }
            }
            __syncthreads();
        }
    }

    int ntop = ctr < NTOP ? ctr : NTOP;
    if (ntop > PRE) ntop = PRE;

    // publish top boxes + areas, release workers
    for (int i = t; i < ntop; i += 1024) {
        u64 k = s_cand[i];
        float4 b = g_boxes[(int)(k & 0xFFFFull)];
        g_topbox[i]  = b;
        g_toparea[i] = __fmul_rn(__fsub_rn(b.z, b.x), __fsub_rn(b.w, b.y));
    }
    if (t == 0) g_ntop = ntop;
    __threadfence();
    __syncthreads();
    if (t == 0) atomicExch(&g_flag2, 1);

    // init rem bits (invalid / beyond ntop) while workers compute masks
    if (t < NCHW) s_rem[t] = 0ull;
    __syncthreads();
    if (t < NTOP) {
        bool bad = (t >= ntop) || ((s_cand[t] >> 47) & 1);
        if (bad) atomicOr(&s_rem[t >> 6], 1ull << (t & 63));
    }

    if (t == 0) { while (atomicAdd(&g_sync3, 0) < NWORK) __nanosleep(64); }
    __syncthreads();
    __threadfence();

    // ================= mask-based greedy scan over top-512 =========================
    int nch = (ntop + 63) >> 6;
    bool done = false;
    for (int c = 0; c < nch; c++) {
        if (t < 64)
            s_intra[t] = (c * 64 + t < ntop) ? g_mask512[(c * 64 + t) * NCHW + c] : 0ull;
        __syncthreads();
        if (t == 0) {
            u64 rem = s_rem[c];
            int kept = s_kept, m_cnt = 0;
            u64 m = ~rem;
            while (m) {
                int b = __ffsll((long long)m) - 1;
                s_keep[kept] = (unsigned short)(c * 64 + b);
                kept++;
                s_wb[m_cnt++] = (unsigned char)b;
                if (kept >= POST) break;
                rem |= s_intra[b];
                m = ~rem & (~0ull << (b + 1));
            }
            s_kept = kept; s_m = m_cnt;
        }
        __syncthreads();
        if (s_kept >= POST) { done = true; break; }
        int nw = nch - 1 - c;
        int mm = s_m;
        for (int p = t; p < mm * nw; p += 1024) {
            int bi2 = p / nw;
            int w   = c + 1 + p - bi2 * nw;
            atomicOr(&s_rem[w], g_mask512[(c * 64 + s_wb[bi2]) * NCHW + w]);
        }
        __syncthreads();
    }

    // materialize kept boxes (needed for output and fallback)
    {
        int kept = s_kept;
        if (t < kept) {
            int r = s_keep[t];
            s_kb[t] = g_topbox[r];
            s_ka[t] = g_toparea[r];
        }
    }
    __syncthreads();

    int processed = ntop;
    last_key = (ntop > 0) ? s_cand[ntop - 1] : 0;

    // ================= generic fallback rounds (never taken on bench data) =========
    if (!done && processed < PRE && processed < total) {
        for (int round = 1; round < MAX_ROUNDS && !done; round++) {
            if (t == 0) { s_H = 0; s_baseH = 0; s_thresh = 0; s_ctr = 0; }
            __syncthreads();
            scan256(t, (t < 256) ? g_hist_hi[t] : 0, s_scan, s_wsum);
            int tot2 = s_scan[255];
            if (processed >= PRE || processed >= tot2) break;
            int tgt = (round + 1) * TOPK_FB;
            if (tgt > tot2) tgt = tot2;
            if (processed >= tgt) continue;
            if (t < 256) {
                int incl = s_scan[t], excl = t ? s_scan[t - 1] : 0;
                if (excl < tgt && incl >= tgt) { s_H = t; s_baseH = excl; }
            }
            __syncthreads();
            int Hb2 = s_H, baseH2 = s_baseH;
            scan256(t, (t < 256) ? g_hist_lo[Hb2 * 256 + t] : 0, s_scan, s_wsum);
            if (t < 256) {
                int incl = baseH2 + s_scan[t], excl = baseH2 + (t ? s_scan[t - 1] : 0);
                if (excl < tgt && incl >= tgt) s_thresh = Hb2 * 256 + t;
            }
            __syncthreads();
            int th2 = s_thresh;
            for (int i = t; i < N_ANCH; i += 1024) {
                u64 k = g_keys[i];
                if (k > last_key && (int)(k >> 32) <= th2) {
                    int p = atomicAdd(&s_ctr, 1);
                    if (p < CAP) s_cand[p] = k;
                }
            }
            __syncthreads();
            int c2 = s_ctr;
            if (c2 > CAP) {
                u64 cur = last_key;
                for (int b = 63; b >= 0; b--) {
                    u64 try_cut = cur | (1ull << b);
                    if (try_cut == cur) continue;
                    int local = 0;
                    for (int i = t; i < N_ANCH; i += 1024) {
                        u64 k = g_keys[i];
                        if (k > last_key && k <= try_cut) local++;
                    }
                    if (t == 0) s_ctr = 0;
                    __syncthreads();
                    atomicAdd(&s_ctr, local);
                    __syncthreads();
                    if (s_ctr <= CAP) cur = try_cut;
                    __syncthreads();
                }
                if (t == 0) s_ctr = 0;
                __syncthreads();
                for (int i = t; i < N_ANCH; i += 1024) {
                    u64 k = g_keys[i];
                    if (k > last_key && k <= cur) {
                        int p = atomicAdd(&s_ctr, 1);
                        s_cand[p] = k;
                    }
                }
                __syncthreads();
                c2 = s_ctr;
            }
            if (c2 == 0) continue;
            for (int p = c2 + t; p < CAP; p += 1024) s_cand[p] = ~0ull;
            __syncthreads();
            for (int k = 2; k <= CAP; k <<= 1) {
                for (int j = k >> 1; j > 0; j >>= 1) {
                    int i   = ((t & ~(j - 1)) << 1) | (t & (j - 1));
                    int ixj = i | j;
                    bool up = ((i & k) == 0);
                    u64 x = s_cand[i], y = s_cand[ixj];
                    if (up ? (x > y) : (x < y)) { s_cand[i] = y; s_cand[ixj] = x; }
                    __syncthreads();
                }
            }
            int n_this = c2;
            if (n_this > PRE - processed) n_this = PRE - processed;
            int nchunks = (n_this + 63) >> 6;
            for (int c = 0; c < nchunks; c++) {
                if (t == 0) s_sup = 0ull;
                __syncthreads();
                if (t < 64) {
                    int pos = c * 64 + t;
                    u64 k = s_cand[pos];
                    bool live = (pos < n_this) && !((k >> 47) & 1);
                    float4 b = live ? g_boxes[(int)(k & 0xFFFFull)]
                                    : make_float4(0.f, 0.f, 0.f, 0.f);
                    s_cb[t] = b;
                    s_ca[t] = __fmul_rn(__fsub_rn(b.z, b.x), __fsub_rn(b.w, b.y));
                    s_intra[t] = 0ull;
                    if (!live) atomicOr(&s_sup, 1ull << t);
                }
                int kept0 = s_kept;
                __syncthreads();
                for (int p = t; p < 64 * kept0; p += 1024) {
                    int b = p & 63, k2i = p >> 6;
                    if (iou_gt(s_kb[k2i], s_ka[k2i], s_cb[b], s_ca[b]))
                        atomicOr(&s_sup, 1ull << b);
                }
                for (int p = t; p < 4096; p += 1024) {
                    int i2 = p >> 6, j2 = p & 63;
                    if (j2 > i2 && iou_gt(s_cb[i2], s_ca[i2], s_cb[j2], s_ca[j2]))
                        atomicOr(&s_intra[i2], 1ull << j2);
                }
                __syncthreads();
                if (t == 0) {
                    u64 rem = s_sup;
                    int kept = kept0;
                    u64 m = ~rem;
                    while (m) {
                        int b = __ffsll((long long)m) - 1;
                        s_kb[kept] = s_cb[b];
                        s_ka[kept] = s_ca[b];
                        kept++;
                        if (kept >= POST) break;
                        rem |= s_intra[b];
                        m = ~rem & (~0ull << (b + 1));
                    }
                    s_kept = kept;
                }
                __syncthreads();
                if (s_kept >= POST) { done = true; break; }
            }
            if (done) break;
            processed += c2;
            if (n_this < c2) break;
            last_key = s_cand[c2 - 1];
            __syncthreads();
        }
    }
    __syncthreads();

    // ================= clears for next replay + output =============================
    {
        int4 z = make_int4(0, 0, 0, 0);
        int4* hl = reinterpret_cast<int4*>(g_hist_lo);
        for (int k = t; k < 65536 / 4; k += 1024) hl[k] = z;
    }
    if (t < 256) g_hist_hi[t] = 0;
    if (t == 0) { g_sync1 = 0; g_flag2 = 0; g_sync3 = 0; }

    int kept = s_kept;
    if (t < POST) {
        float4 v = make_float4(0.f, 0.f, 0.f, 0.f);
        if (t < kept) v = s_kb[t];
        reinterpret_cast<float4*>(out)[t] = v;
    }
}

// ---------------- launch ----------------
extern "C" void kernel_launch(void* const* d_in, const int* in_sizes, int n_in,
                              void* d_out, int out_size)
{
    const float4* anchors = (const float4*)d_in[0];
    const float*  cls     = (const float*)d_in[1];
    const float4* reg     = (const float4*)d_in[2];
    const int*    img_w   = (n_in > 3) ? (const int*)d_in[3] : nullptr;
    const int*    img_h   = (n_in > 4) ? (const int*)d_in[4] : nullptr;
    int have_wh = (n_in > 4) ? 1 : 0;

    fused_kernel<<<NBLK, 1024>>>(anchors, cls, reg, img_w, img_h, have_wh, (float*)d_out);
}